// round 1
// baseline (speedup 1.0000x reference)
#include <cuda_runtime.h>

// Problem constants
#define F   16
#define HID 64
#define NN  100000
#define EE  3200000
#define ROUNDS 5

typedef unsigned long long ull;

// ---------------- scratch (device globals; no allocations allowed) ----------
__device__ __align__(256) float g_edges[(size_t)F * EE];   // [F][E] row-major, 204.8 MB
__device__ __align__(256) float g_nodes[F * NN];           // [F][N] row-major
__device__ __align__(256) float g_sent[NN * F];            // [N][F] column-major agg
__device__ __align__(256) float g_recv[NN * F];            // [N][F]
__device__ __align__(256) float g_ps[NN * HID];            // [N][HID]  eW1_s @ nodes + eb1
__device__ __align__(256) float g_pr[NN * HID];            // [N][HID]  eW1_r @ nodes

// ---------------- packed f32x2 helpers --------------------------------------
__device__ __forceinline__ ull pack2(float a, float b) {
    ull r; asm("mov.b64 %0, {%1,%2};" : "=l"(r) : "f"(a), "f"(b)); return r;
}
__device__ __forceinline__ void unpack2(ull v, float& a, float& b) {
    asm("mov.b64 {%0,%1}, %2;" : "=f"(a), "=f"(b) : "l"(v));
}
__device__ __forceinline__ ull fma2(ull a, ull b, ull c) {
    ull d; asm("fma.rn.f32x2 %0, %1, %2, %3;" : "=l"(d) : "l"(a), "l"(b), "l"(c)); return d;
}
__device__ __forceinline__ ull add2(ull a, ull b) {
    ull d; asm("add.rn.f32x2 %0, %1, %2;" : "=l"(d) : "l"(a), "l"(b)); return d;
}

// ---------------- copy in / out ---------------------------------------------
__global__ void copyin_kernel(const float* __restrict__ nodes, const float* __restrict__ edges) {
    const int n4_nodes = (F * NN) / 4;
    const int n4_edges = (F * EE) / 4;
    float4* gn = reinterpret_cast<float4*>(g_nodes);
    float4* ge = reinterpret_cast<float4*>(g_edges);
    const float4* sn = reinterpret_cast<const float4*>(nodes);
    const float4* se = reinterpret_cast<const float4*>(edges);
    for (int i = blockIdx.x * blockDim.x + threadIdx.x; i < n4_nodes; i += gridDim.x * blockDim.x)
        gn[i] = sn[i];
    for (int i = blockIdx.x * blockDim.x + threadIdx.x; i < n4_edges; i += gridDim.x * blockDim.x)
        ge[i] = se[i];
}

__global__ void copyout_kernel(float* __restrict__ out) {
    const int n4_nodes = (F * NN) / 4;
    const int n4_edges = (F * EE) / 4;
    const float4* gn = reinterpret_cast<const float4*>(g_nodes);
    const float4* ge = reinterpret_cast<const float4*>(g_edges);
    float4* on = reinterpret_cast<float4*>(out);
    float4* oe = reinterpret_cast<float4*>(out + F * NN);
    for (int i = blockIdx.x * blockDim.x + threadIdx.x; i < n4_nodes; i += gridDim.x * blockDim.x)
        on[i] = gn[i];
    for (int i = blockIdx.x * blockDim.x + threadIdx.x; i < n4_edges; i += gridDim.x * blockDim.x)
        oe[i] = ge[i];
}

// ---------------- zero aggregation buffers ----------------------------------
__global__ void zero_agg_kernel() {
    int i = blockIdx.x * blockDim.x + threadIdx.x;
    const int n4 = (NN * F) / 4;
    float4 z = make_float4(0.f, 0.f, 0.f, 0.f);
    if (i < n4) {
        reinterpret_cast<float4*>(g_sent)[i] = z;
        reinterpret_cast<float4*>(g_recv)[i] = z;
    }
}

// ---------------- scatter: edges -> sent/recv aggregates --------------------
__global__ void scatter_kernel(const int* __restrict__ snd, const int* __restrict__ rcv) {
    int e = blockIdx.x * blockDim.x + threadIdx.x;
    if (e >= EE) return;
    int s = snd[e];
    int r = rcv[e];
    float v[F];
#pragma unroll
    for (int f = 0; f < F; f++) v[f] = __ldcs(&g_edges[(size_t)f * EE + e]);
    float* ps = &g_sent[(size_t)s * F];
    float* pr = &g_recv[(size_t)r * F];
#pragma unroll
    for (int f = 0; f < F; f += 4) {
        asm volatile("red.global.add.v4.f32 [%0], {%1,%2,%3,%4};"
                     :: "l"(ps + f), "f"(v[f]), "f"(v[f + 1]), "f"(v[f + 2]), "f"(v[f + 3])
                     : "memory");
        asm volatile("red.global.add.v4.f32 [%0], {%1,%2,%3,%4};"
                     :: "l"(pr + f), "f"(v[f]), "f"(v[f + 1]), "f"(v[f + 2]), "f"(v[f + 3])
                     : "memory");
    }
}

// ---------------- node MLP: [nodes; sent; recv] 48 -> 64 -> 16 (in place) ---
__global__ void node_mlp_kernel(const float* __restrict__ W1, const float* __restrict__ b1,
                                const float* __restrict__ W2, const float* __restrict__ b2) {
    __shared__ __align__(16) float s_w1t[48 * HID];  // [k][h]
    __shared__ __align__(16) float s_w2t[HID * F];   // [h][o]
    __shared__ float s_b1[HID];
    __shared__ float s_b2[F];
    for (int i = threadIdx.x; i < 48 * HID; i += blockDim.x) {
        int k = i >> 6, h = i & 63;
        s_w1t[i] = W1[h * 48 + k];
    }
    for (int i = threadIdx.x; i < HID * F; i += blockDim.x) {
        int h = i >> 4, o = i & 15;
        s_w2t[i] = W2[o * HID + h];
    }
    if (threadIdx.x < HID) s_b1[threadIdx.x] = b1[threadIdx.x];
    if (threadIdx.x < F)   s_b2[threadIdx.x] = b2[threadIdx.x];
    __syncthreads();

    int n = blockIdx.x * blockDim.x + threadIdx.x;
    if (n >= NN) return;

    ull acc[HID / 2];
#pragma unroll
    for (int j = 0; j < HID / 2; j++) acc[j] = pack2(s_b1[2 * j], s_b1[2 * j + 1]);

#pragma unroll
    for (int k = 0; k < 48; k++) {
        float xk;
        if (k < 16)      xk = g_nodes[(size_t)k * NN + n];
        else if (k < 32) xk = g_sent[(size_t)n * F + (k - 16)];
        else             xk = g_recv[(size_t)n * F + (k - 32)];
        ull xs = pack2(xk, xk);
        const ull* w = reinterpret_cast<const ull*>(&s_w1t[k * HID]);
#pragma unroll
        for (int j = 0; j < HID / 2; j++) acc[j] = fma2(w[j], xs, acc[j]);
    }

    ull o[F / 2];
#pragma unroll
    for (int j = 0; j < F / 2; j++) o[j] = pack2(s_b2[2 * j], s_b2[2 * j + 1]);
#pragma unroll
    for (int h = 0; h < HID; h += 2) {
        float h0, h1; unpack2(acc[h >> 1], h0, h1);
        h0 = fmaxf(h0, 0.f); h1 = fmaxf(h1, 0.f);
        ull x0 = pack2(h0, h0), x1 = pack2(h1, h1);
        const ull* w0 = reinterpret_cast<const ull*>(&s_w2t[h * F]);
        const ull* w1 = reinterpret_cast<const ull*>(&s_w2t[(h + 1) * F]);
#pragma unroll
        for (int j = 0; j < F / 2; j++) { o[j] = fma2(w0[j], x0, o[j]); o[j] = fma2(w1[j], x1, o[j]); }
    }
#pragma unroll
    for (int k = 0; k < F; k += 2) {
        float a, b; unpack2(o[k >> 1], a, b);
        g_nodes[(size_t)k * NN + n]       = a;
        g_nodes[(size_t)(k + 1) * NN + n] = b;
    }
}

// ---------------- projections: Ps = eW1_s@nodes + eb1, Pr = eW1_r@nodes -----
__global__ void proj_kernel(const float* __restrict__ eW1, const float* __restrict__ eb1) {
    __shared__ __align__(16) float s_ws[16 * HID];  // [k][h], cols 16..31 of eW1
    __shared__ __align__(16) float s_wr[16 * HID];  // [k][h], cols 32..47
    __shared__ float s_b1[HID];
    for (int i = threadIdx.x; i < 16 * HID; i += blockDim.x) {
        int k = i >> 6, h = i & 63;
        s_ws[i] = eW1[h * 48 + 16 + k];
        s_wr[i] = eW1[h * 48 + 32 + k];
    }
    if (threadIdx.x < HID) s_b1[threadIdx.x] = eb1[threadIdx.x];
    __syncthreads();

    int n = blockIdx.x * blockDim.x + threadIdx.x;
    if (n >= NN) return;

    float x[16];
#pragma unroll
    for (int k = 0; k < 16; k++) x[k] = g_nodes[(size_t)k * NN + n];

    ull acc[HID / 2];
#pragma unroll
    for (int j = 0; j < HID / 2; j++) acc[j] = pack2(s_b1[2 * j], s_b1[2 * j + 1]);
#pragma unroll
    for (int k = 0; k < 16; k++) {
        ull xs = pack2(x[k], x[k]);
        const ull* w = reinterpret_cast<const ull*>(&s_ws[k * HID]);
#pragma unroll
        for (int j = 0; j < HID / 2; j++) acc[j] = fma2(w[j], xs, acc[j]);
    }
    ull* outp = reinterpret_cast<ull*>(&g_ps[(size_t)n * HID]);
#pragma unroll
    for (int j = 0; j < HID / 2; j++) outp[j] = acc[j];

#pragma unroll
    for (int j = 0; j < HID / 2; j++) acc[j] = 0ull;
#pragma unroll
    for (int k = 0; k < 16; k++) {
        ull xs = pack2(x[k], x[k]);
        const ull* w = reinterpret_cast<const ull*>(&s_wr[k * HID]);
#pragma unroll
        for (int j = 0; j < HID / 2; j++) acc[j] = fma2(w[j], xs, acc[j]);
    }
    outp = reinterpret_cast<ull*>(&g_pr[(size_t)n * HID]);
#pragma unroll
    for (int j = 0; j < HID / 2; j++) outp[j] = acc[j];
}

// ---------------- edge MLP: eW1_e@edge + Ps[s] + Pr[r] -> relu -> eW2 -------
__global__ void edge_mlp_kernel(const int* __restrict__ snd, const int* __restrict__ rcv,
                                const float* __restrict__ eW1, const float* __restrict__ eW2,
                                const float* __restrict__ eb2) {
    __shared__ __align__(16) float s_w1t[16 * HID];  // [k][h], cols 0..15 of eW1
    __shared__ __align__(16) float s_w2t[HID * F];   // [h][o]
    __shared__ float s_b2[F];
    for (int i = threadIdx.x; i < 16 * HID; i += blockDim.x) {
        int k = i >> 6, h = i & 63;
        s_w1t[i] = eW1[h * 48 + k];
    }
    for (int i = threadIdx.x; i < HID * F; i += blockDim.x) {
        int h = i >> 4, o = i & 15;
        s_w2t[i] = eW2[o * HID + h];
    }
    if (threadIdx.x < F) s_b2[threadIdx.x] = eb2[threadIdx.x];
    __syncthreads();

    int e = blockIdx.x * blockDim.x + threadIdx.x;
    if (e >= EE) return;
    int s = snd[e];
    int r = rcv[e];

    const ull* pp = reinterpret_cast<const ull*>(&g_ps[(size_t)s * HID]);
    const ull* qq = reinterpret_cast<const ull*>(&g_pr[(size_t)r * HID]);
    ull acc[HID / 2];
#pragma unroll
    for (int j = 0; j < HID / 2; j++) acc[j] = add2(pp[j], qq[j]);

#pragma unroll
    for (int k = 0; k < 16; k++) {
        float xk = __ldcs(&g_edges[(size_t)k * EE + e]);   // streaming: protect Ps/Pr in L2
        ull xs = pack2(xk, xk);
        const ull* w = reinterpret_cast<const ull*>(&s_w1t[k * HID]);
#pragma unroll
        for (int j = 0; j < HID / 2; j++) acc[j] = fma2(w[j], xs, acc[j]);
    }

    ull o[F / 2];
#pragma unroll
    for (int j = 0; j < F / 2; j++) o[j] = pack2(s_b2[2 * j], s_b2[2 * j + 1]);
#pragma unroll
    for (int h = 0; h < HID; h += 2) {
        float h0, h1; unpack2(acc[h >> 1], h0, h1);
        h0 = fmaxf(h0, 0.f); h1 = fmaxf(h1, 0.f);
        ull x0 = pack2(h0, h0), x1 = pack2(h1, h1);
        const ull* w0 = reinterpret_cast<const ull*>(&s_w2t[h * F]);
        const ull* w1 = reinterpret_cast<const ull*>(&s_w2t[(h + 1) * F]);
#pragma unroll
        for (int j = 0; j < F / 2; j++) { o[j] = fma2(w0[j], x0, o[j]); o[j] = fma2(w1[j], x1, o[j]); }
    }
#pragma unroll
    for (int k = 0; k < F; k += 2) {
        float a, b; unpack2(o[k >> 1], a, b);
        __stcs(&g_edges[(size_t)k * EE + e], a);
        __stcs(&g_edges[(size_t)(k + 1) * EE + e], b);
    }
}

// ---------------- launch ------------------------------------------------------
extern "C" void kernel_launch(void* const* d_in, const int* in_sizes, int n_in,
                              void* d_out, int out_size) {
    const float* nodes     = (const float*)d_in[0];
    const float* edges     = (const float*)d_in[1];
    const int*   receivers = (const int*)  d_in[2];
    const int*   senders   = (const int*)  d_in[3];
    const float* nW1 = (const float*)d_in[4];
    const float* nb1 = (const float*)d_in[5];
    const float* nW2 = (const float*)d_in[6];
    const float* nb2 = (const float*)d_in[7];
    const float* eW1 = (const float*)d_in[8];
    const float* eb1 = (const float*)d_in[9];
    const float* eW2 = (const float*)d_in[10];
    const float* eb2 = (const float*)d_in[11];
    float* out = (float*)d_out;

    const int TPB = 256;
    const int EDGE_BLOCKS = (EE + TPB - 1) / TPB;   // 12500
    const int NODE_BLOCKS = (NN + TPB - 1) / TPB;   // 391
    const int ZERO_BLOCKS = ((NN * F) / 4 + TPB - 1) / TPB;

    copyin_kernel<<<2048, TPB>>>(nodes, edges);

    for (int round = 0; round < ROUNDS; round++) {
        zero_agg_kernel<<<ZERO_BLOCKS, TPB>>>();
        scatter_kernel<<<EDGE_BLOCKS, TPB>>>(senders, receivers);
        node_mlp_kernel<<<NODE_BLOCKS, TPB>>>(nW1, nb1, nW2, nb2);
        proj_kernel<<<NODE_BLOCKS, TPB>>>(eW1, eb1);
        edge_mlp_kernel<<<EDGE_BLOCKS, TPB>>>(senders, receivers, eW1, eW2, eb2);
    }

    copyout_kernel<<<2048, TPB>>>(out);
}

// round 2
// speedup vs baseline: 1.3592x; 1.3592x over previous
#include <cuda_runtime.h>

#define F   16
#define HID 64
#define NN  100000
#define EE  3200000
#define ROUNDS 5

typedef unsigned long long ull;

// ---------------- scratch (device globals; no allocations allowed) ----------
__device__ __align__(256) float g_edges[(size_t)F * EE];   // [F][E]
__device__ __align__(256) float g_nodes[F * NN];           // [F][N]
__device__ __align__(256) float g_sent[NN * F];            // [N][F]
__device__ __align__(256) float g_recv[NN * F];            // [N][F]
__device__ __align__(256) float g_ps[NN * HID];            // [N][HID]  eW1_s @ nodes + eb1
__device__ __align__(256) float g_pr[NN * HID];            // [N][HID]  eW1_r @ nodes

// ---------------- packed f32x2 helpers --------------------------------------
__device__ __forceinline__ ull pack2(float a, float b) {
    ull r; asm("mov.b64 %0, {%1,%2};" : "=l"(r) : "f"(a), "f"(b)); return r;
}
__device__ __forceinline__ void unpack2(ull v, float& a, float& b) {
    asm("mov.b64 {%0,%1}, %2;" : "=f"(a), "=f"(b) : "l"(v));
}
__device__ __forceinline__ ull fma2(ull a, ull b, ull c) {
    ull d; asm("fma.rn.f32x2 %0, %1, %2, %3;" : "=l"(d) : "l"(a), "l"(b), "l"(c)); return d;
}
__device__ __forceinline__ ull add2(ull a, ull b) {
    ull d; asm("add.rn.f32x2 %0, %1, %2;" : "=l"(d) : "l"(a), "l"(b)); return d;
}

// ---------------- copy in / out ---------------------------------------------
__global__ void copyin_kernel(const float* __restrict__ nodes, const float* __restrict__ edges) {
    const int n4_nodes = (F * NN) / 4;
    const int n4_edges = (F * EE) / 4;
    float4* gn = reinterpret_cast<float4*>(g_nodes);
    float4* ge = reinterpret_cast<float4*>(g_edges);
    const float4* sn = reinterpret_cast<const float4*>(nodes);
    const float4* se = reinterpret_cast<const float4*>(edges);
    for (int i = blockIdx.x * blockDim.x + threadIdx.x; i < n4_nodes; i += gridDim.x * blockDim.x)
        gn[i] = sn[i];
    for (int i = blockIdx.x * blockDim.x + threadIdx.x; i < n4_edges; i += gridDim.x * blockDim.x)
        ge[i] = se[i];
}

__global__ void copyout_kernel(float* __restrict__ out) {
    const int n4_nodes = (F * NN) / 4;
    const int n4_edges = (F * EE) / 4;
    const float4* gn = reinterpret_cast<const float4*>(g_nodes);
    const float4* ge = reinterpret_cast<const float4*>(g_edges);
    float4* on = reinterpret_cast<float4*>(out);
    float4* oe = reinterpret_cast<float4*>(out + F * NN);
    for (int i = blockIdx.x * blockDim.x + threadIdx.x; i < n4_nodes; i += gridDim.x * blockDim.x)
        on[i] = gn[i];
    for (int i = blockIdx.x * blockDim.x + threadIdx.x; i < n4_edges; i += gridDim.x * blockDim.x)
        oe[i] = ge[i];
}

// ---------------- zero aggregation buffers ----------------------------------
__global__ void zero_agg_kernel() {
    int i = blockIdx.x * blockDim.x + threadIdx.x;
    const int n4 = (NN * F) / 4;
    float4 z = make_float4(0.f, 0.f, 0.f, 0.f);
    if (i < n4) {
        reinterpret_cast<float4*>(g_sent)[i] = z;
        reinterpret_cast<float4*>(g_recv)[i] = z;
    }
}

// ---------------- round-0 scatter: initial edges -> aggregates --------------
__global__ void scatter_kernel(const int* __restrict__ snd, const int* __restrict__ rcv) {
    int e = blockIdx.x * blockDim.x + threadIdx.x;
    if (e >= EE) return;
    int s = snd[e];
    int r = rcv[e];
    float v[F];
#pragma unroll
    for (int f = 0; f < F; f++) v[f] = __ldcs(&g_edges[(size_t)f * EE + e]);
    float* ps = &g_sent[(size_t)s * F];
    float* pr = &g_recv[(size_t)r * F];
#pragma unroll
    for (int f = 0; f < F; f += 4) {
        asm volatile("red.global.add.v4.f32 [%0], {%1,%2,%3,%4};"
                     :: "l"(ps + f), "f"(v[f]), "f"(v[f + 1]), "f"(v[f + 2]), "f"(v[f + 3])
                     : "memory");
        asm volatile("red.global.add.v4.f32 [%0], {%1,%2,%3,%4};"
                     :: "l"(pr + f), "f"(v[f]), "f"(v[f + 1]), "f"(v[f + 2]), "f"(v[f + 3])
                     : "memory");
    }
}

// ---------------- node MLP: [nodes; sent; recv] 48 -> 64 -> 16 (in place) ---
__global__ void __launch_bounds__(256)
node_mlp_kernel(const float* __restrict__ W1, const float* __restrict__ b1,
                const float* __restrict__ W2, const float* __restrict__ b2) {
    __shared__ __align__(16) float s_w1t[48 * HID];  // [k][h]
    __shared__ __align__(16) float s_w2t[HID * F];   // [h][o]
    __shared__ __align__(16) float s_b1[HID];
    __shared__ __align__(16) float s_b2[F];
    for (int i = threadIdx.x; i < 48 * HID; i += blockDim.x) {
        int k = i >> 6, h = i & 63;
        s_w1t[i] = W1[h * 48 + k];
    }
    for (int i = threadIdx.x; i < HID * F; i += blockDim.x) {
        int h = i >> 4, o = i & 15;
        s_w2t[i] = W2[o * HID + h];
    }
    if (threadIdx.x < HID) s_b1[threadIdx.x] = b1[threadIdx.x];
    if (threadIdx.x < F)   s_b2[threadIdx.x] = b2[threadIdx.x];
    __syncthreads();

    int n = blockIdx.x * blockDim.x + threadIdx.x;
    if (n >= NN) return;

    ull acc[HID / 2];
#pragma unroll
    for (int j = 0; j < HID / 4; j++) {
        ulonglong2 bv = *reinterpret_cast<const ulonglong2*>(&s_b1[j * 4]);
        acc[2 * j] = bv.x; acc[2 * j + 1] = bv.y;
    }

    // segment 0: current node features (coalesced column loads)
#pragma unroll
    for (int k = 0; k < 16; k++) {
        float xk = g_nodes[(size_t)k * NN + n];
        ull xs = pack2(xk, xk);
        const ulonglong2* w = reinterpret_cast<const ulonglong2*>(&s_w1t[k * HID]);
#pragma unroll
        for (int m = 0; m < 16; m++) {
            ulonglong2 wv = w[m];
            acc[2 * m]     = fma2(wv.x, xs, acc[2 * m]);
            acc[2 * m + 1] = fma2(wv.y, xs, acc[2 * m + 1]);
        }
    }
    // segment 1: sent aggregate (vector row loads)
    {
        float xv[16];
#pragma unroll
        for (int q = 0; q < 4; q++) {
            float4 v = *reinterpret_cast<const float4*>(&g_sent[(size_t)n * F + q * 4]);
            xv[q * 4] = v.x; xv[q * 4 + 1] = v.y; xv[q * 4 + 2] = v.z; xv[q * 4 + 3] = v.w;
        }
#pragma unroll
        for (int k = 0; k < 16; k++) {
            ull xs = pack2(xv[k], xv[k]);
            const ulonglong2* w = reinterpret_cast<const ulonglong2*>(&s_w1t[(16 + k) * HID]);
#pragma unroll
            for (int m = 0; m < 16; m++) {
                ulonglong2 wv = w[m];
                acc[2 * m]     = fma2(wv.x, xs, acc[2 * m]);
                acc[2 * m + 1] = fma2(wv.y, xs, acc[2 * m + 1]);
            }
        }
    }
    // segment 2: recv aggregate
    {
        float xv[16];
#pragma unroll
        for (int q = 0; q < 4; q++) {
            float4 v = *reinterpret_cast<const float4*>(&g_recv[(size_t)n * F + q * 4]);
            xv[q * 4] = v.x; xv[q * 4 + 1] = v.y; xv[q * 4 + 2] = v.z; xv[q * 4 + 3] = v.w;
        }
#pragma unroll
        for (int k = 0; k < 16; k++) {
            ull xs = pack2(xv[k], xv[k]);
            const ulonglong2* w = reinterpret_cast<const ulonglong2*>(&s_w1t[(32 + k) * HID]);
#pragma unroll
            for (int m = 0; m < 16; m++) {
                ulonglong2 wv = w[m];
                acc[2 * m]     = fma2(wv.x, xs, acc[2 * m]);
                acc[2 * m + 1] = fma2(wv.y, xs, acc[2 * m + 1]);
            }
        }
    }

    ull o[F / 2];
#pragma unroll
    for (int j = 0; j < 4; j++) {
        ulonglong2 bv = *reinterpret_cast<const ulonglong2*>(&s_b2[j * 4]);
        o[2 * j] = bv.x; o[2 * j + 1] = bv.y;
    }
#pragma unroll
    for (int h = 0; h < HID; h += 2) {
        float h0, h1; unpack2(acc[h >> 1], h0, h1);
        h0 = fmaxf(h0, 0.f); h1 = fmaxf(h1, 0.f);
        ull x0 = pack2(h0, h0), x1 = pack2(h1, h1);
        const ulonglong2* w0 = reinterpret_cast<const ulonglong2*>(&s_w2t[h * F]);
        const ulonglong2* w1 = reinterpret_cast<const ulonglong2*>(&s_w2t[(h + 1) * F]);
#pragma unroll
        for (int m = 0; m < 4; m++) {
            ulonglong2 a = w0[m], b = w1[m];
            o[2 * m]     = fma2(a.x, x0, o[2 * m]);
            o[2 * m]     = fma2(b.x, x1, o[2 * m]);
            o[2 * m + 1] = fma2(a.y, x0, o[2 * m + 1]);
            o[2 * m + 1] = fma2(b.y, x1, o[2 * m + 1]);
        }
    }
#pragma unroll
    for (int k = 0; k < F; k += 2) {
        float a, b; unpack2(o[k >> 1], a, b);
        g_nodes[(size_t)k * NN + n]       = a;
        g_nodes[(size_t)(k + 1) * NN + n] = b;
    }
}

// ---------------- projections: Ps = eW1_s@nodes + eb1, Pr = eW1_r@nodes -----
__global__ void __launch_bounds__(256)
proj_kernel(const float* __restrict__ eW1, const float* __restrict__ eb1) {
    __shared__ __align__(16) float s_ws[16 * HID];  // [k][h], cols 16..31 of eW1
    __shared__ __align__(16) float s_wr[16 * HID];  // [k][h], cols 32..47
    __shared__ __align__(16) float s_b1[HID];
    for (int i = threadIdx.x; i < 16 * HID; i += blockDim.x) {
        int k = i >> 6, h = i & 63;
        s_ws[i] = eW1[h * 48 + 16 + k];
        s_wr[i] = eW1[h * 48 + 32 + k];
    }
    if (threadIdx.x < HID) s_b1[threadIdx.x] = eb1[threadIdx.x];
    __syncthreads();

    int n = blockIdx.x * blockDim.x + threadIdx.x;
    if (n >= NN) return;

    float x[16];
#pragma unroll
    for (int k = 0; k < 16; k++) x[k] = g_nodes[(size_t)k * NN + n];

    ull acc[HID / 2];
#pragma unroll
    for (int j = 0; j < HID / 4; j++) {
        ulonglong2 bv = *reinterpret_cast<const ulonglong2*>(&s_b1[j * 4]);
        acc[2 * j] = bv.x; acc[2 * j + 1] = bv.y;
    }
#pragma unroll
    for (int k = 0; k < 16; k++) {
        ull xs = pack2(x[k], x[k]);
        const ulonglong2* w = reinterpret_cast<const ulonglong2*>(&s_ws[k * HID]);
#pragma unroll
        for (int m = 0; m < 16; m++) {
            ulonglong2 wv = w[m];
            acc[2 * m]     = fma2(wv.x, xs, acc[2 * m]);
            acc[2 * m + 1] = fma2(wv.y, xs, acc[2 * m + 1]);
        }
    }
    ull* outp = reinterpret_cast<ull*>(&g_ps[(size_t)n * HID]);
#pragma unroll
    for (int j = 0; j < HID / 2; j++) outp[j] = acc[j];

#pragma unroll
    for (int j = 0; j < HID / 2; j++) acc[j] = 0ull;
#pragma unroll
    for (int k = 0; k < 16; k++) {
        ull xs = pack2(x[k], x[k]);
        const ulonglong2* w = reinterpret_cast<const ulonglong2*>(&s_wr[k * HID]);
#pragma unroll
        for (int m = 0; m < 16; m++) {
            ulonglong2 wv = w[m];
            acc[2 * m]     = fma2(wv.x, xs, acc[2 * m]);
            acc[2 * m + 1] = fma2(wv.y, xs, acc[2 * m + 1]);
        }
    }
    outp = reinterpret_cast<ull*>(&g_pr[(size_t)n * HID]);
#pragma unroll
    for (int j = 0; j < HID / 2; j++) outp[j] = acc[j];
}

// ---------------- edge MLP (fused gather-stage + MLP + scatter) --------------
// smem layout (floats): s_g[256][68] | s_w1t[16*64] | s_w2t[64*16] | s_b2[16]
#define SG_STRIDE 68
#define EDGE_SMEM_FLOATS (256 * SG_STRIDE + 16 * 64 + 64 * 16 + 16)

__global__ void __launch_bounds__(256, 2)
edge_mlp_kernel(const int* __restrict__ snd, const int* __restrict__ rcv,
                const float* __restrict__ eW1, const float* __restrict__ eW2,
                const float* __restrict__ eb2, int do_scatter) {
    extern __shared__ __align__(16) float smem[];
    float* s_g   = smem;                         // 256*68
    float* s_w1t = smem + 256 * SG_STRIDE;       // [k][h]
    float* s_w2t = s_w1t + 16 * 64;              // [h][o]
    float* s_b2  = s_w2t + 64 * 16;              // 16

    const int tid = threadIdx.x;
    for (int i = tid; i < 16 * 64; i += 256) { int k = i >> 6, h = i & 63; s_w1t[i] = eW1[h * 48 + k]; }
    for (int i = tid; i < 64 * 16; i += 256) { int h = i >> 4, o = i & 15; s_w2t[i] = eW2[o * 64 + h]; }
    if (tid < 16) s_b2[tid] = eb2[tid];

    const int e0 = blockIdx.x * 256;

    // ---- cooperative gather staging: s_g[el][h] = g_ps[s_el][h] + g_pr[r_el][h]
    {
        const int wid  = tid >> 5;
        const int lane = tid & 31;
        const int sub  = lane >> 4;   // which of 2 edges this half-warp handles
        const int c    = lane & 15;   // 16B chunk within the 256B row
#pragma unroll
        for (int i = 0; i < 32; i += 2) {
            int el = wid * 32 + i + sub;
            int s = snd[e0 + el];
            int r = rcv[e0 + el];
            ulonglong2 a = *reinterpret_cast<const ulonglong2*>(&g_ps[(size_t)s * HID + c * 4]);
            ulonglong2 b = *reinterpret_cast<const ulonglong2*>(&g_pr[(size_t)r * HID + c * 4]);
            ulonglong2 v; v.x = add2(a.x, b.x); v.y = add2(a.y, b.y);
            *reinterpret_cast<ulonglong2*>(&s_g[el * SG_STRIDE + c * 4]) = v;
        }
    }
    __syncthreads();

    const size_t e = (size_t)e0 + tid;

    // ---- layer 1 accumulators initialized from staged gather (bias folded in g_ps)
    ull acc[HID / 2];
    {
        const float* grow = &s_g[tid * SG_STRIDE];
#pragma unroll
        for (int m = 0; m < 16; m++) {
            ulonglong2 v = *reinterpret_cast<const ulonglong2*>(&grow[m * 4]);
            acc[2 * m] = v.x; acc[2 * m + 1] = v.y;
        }
    }

    // ---- layer 1: += eW1_e @ edge
#pragma unroll
    for (int k = 0; k < 16; k++) {
        float x = __ldcs(&g_edges[(size_t)k * EE + e]);
        ull xs = pack2(x, x);
        const ulonglong2* w = reinterpret_cast<const ulonglong2*>(&s_w1t[k * HID]);
#pragma unroll
        for (int m = 0; m < 16; m++) {
            ulonglong2 wv = w[m];
            acc[2 * m]     = fma2(wv.x, xs, acc[2 * m]);
            acc[2 * m + 1] = fma2(wv.y, xs, acc[2 * m + 1]);
        }
    }

    // ---- layer 2: relu -> 16 outputs
    ull o[F / 2];
#pragma unroll
    for (int j = 0; j < 4; j++) {
        ulonglong2 bv = *reinterpret_cast<const ulonglong2*>(&s_b2[j * 4]);
        o[2 * j] = bv.x; o[2 * j + 1] = bv.y;
    }
#pragma unroll
    for (int h = 0; h < HID; h += 2) {
        float h0, h1; unpack2(acc[h >> 1], h0, h1);
        h0 = fmaxf(h0, 0.f); h1 = fmaxf(h1, 0.f);
        ull x0 = pack2(h0, h0), x1 = pack2(h1, h1);
        const ulonglong2* w0 = reinterpret_cast<const ulonglong2*>(&s_w2t[h * F]);
        const ulonglong2* w1 = reinterpret_cast<const ulonglong2*>(&s_w2t[(h + 1) * F]);
#pragma unroll
        for (int m = 0; m < 4; m++) {
            ulonglong2 a = w0[m], b = w1[m];
            o[2 * m]     = fma2(a.x, x0, o[2 * m]);
            o[2 * m]     = fma2(b.x, x1, o[2 * m]);
            o[2 * m + 1] = fma2(a.y, x0, o[2 * m + 1]);
            o[2 * m + 1] = fma2(b.y, x1, o[2 * m + 1]);
        }
    }

    float ov[F];
#pragma unroll
    for (int j = 0; j < F / 2; j++) unpack2(o[j], ov[2 * j], ov[2 * j + 1]);

    // write new edge features (streaming)
#pragma unroll
    for (int f = 0; f < F; f++) __stcs(&g_edges[(size_t)f * EE + e], ov[f]);

    // fused scatter into next round's aggregates
    if (do_scatter) {
        int s = snd[e];
        int r = rcv[e];
        float* ps = &g_sent[(size_t)s * F];
        float* pr = &g_recv[(size_t)r * F];
#pragma unroll
        for (int f = 0; f < F; f += 4) {
            asm volatile("red.global.add.v4.f32 [%0], {%1,%2,%3,%4};"
                         :: "l"(ps + f), "f"(ov[f]), "f"(ov[f + 1]), "f"(ov[f + 2]), "f"(ov[f + 3])
                         : "memory");
            asm volatile("red.global.add.v4.f32 [%0], {%1,%2,%3,%4};"
                         :: "l"(pr + f), "f"(ov[f]), "f"(ov[f + 1]), "f"(ov[f + 2]), "f"(ov[f + 3])
                         : "memory");
        }
    }
}

// ---------------- launch ------------------------------------------------------
extern "C" void kernel_launch(void* const* d_in, const int* in_sizes, int n_in,
                              void* d_out, int out_size) {
    const float* nodes     = (const float*)d_in[0];
    const float* edges     = (const float*)d_in[1];
    const int*   receivers = (const int*)  d_in[2];
    const int*   senders   = (const int*)  d_in[3];
    const float* nW1 = (const float*)d_in[4];
    const float* nb1 = (const float*)d_in[5];
    const float* nW2 = (const float*)d_in[6];
    const float* nb2 = (const float*)d_in[7];
    const float* eW1 = (const float*)d_in[8];
    const float* eb1 = (const float*)d_in[9];
    const float* eW2 = (const float*)d_in[10];
    const float* eb2 = (const float*)d_in[11];
    float* out = (float*)d_out;

    const int TPB = 256;
    const int EDGE_BLOCKS = EE / TPB;               // 12500 (exact)
    const int NODE_BLOCKS = (NN + TPB - 1) / TPB;   // 391
    const int ZERO_BLOCKS = ((NN * F) / 4 + TPB - 1) / TPB;
    const int EDGE_SMEM = EDGE_SMEM_FLOATS * 4;     // 77888 bytes

    cudaFuncSetAttribute(edge_mlp_kernel, cudaFuncAttributeMaxDynamicSharedMemorySize, EDGE_SMEM);

    copyin_kernel<<<2048, TPB>>>(nodes, edges);

    // round-0 aggregation from initial edges
    zero_agg_kernel<<<ZERO_BLOCKS, TPB>>>();
    scatter_kernel<<<EDGE_BLOCKS, TPB>>>(senders, receivers);

    for (int round = 0; round < ROUNDS; round++) {
        node_mlp_kernel<<<NODE_BLOCKS, TPB>>>(nW1, nb1, nW2, nb2);
        proj_kernel<<<NODE_BLOCKS, TPB>>>(eW1, eb1);
        int do_scatter = (round < ROUNDS - 1);
        if (do_scatter) zero_agg_kernel<<<ZERO_BLOCKS, TPB>>>();
        edge_mlp_kernel<<<EDGE_BLOCKS, TPB, EDGE_SMEM>>>(senders, receivers, eW1, eW2, eb2, do_scatter);
    }

    copyout_kernel<<<2048, TPB>>>(out);
}